// round 12
// baseline (speedup 1.0000x reference)
#include <cuda_runtime.h>
#include <cuda_fp16.h>
#include <cstdint>

// ---------------- problem constants ----------------
#define Hh   1024
#define SQ   512
#define BBat 256
#define CCls 10

// ---------------- kernel config ----------------
#define NCTA   128
#define TPB    256
#define BH     128           // batch rows per CTA
#define NCOLS  64            // 16 hidden units * 4 gates
#define UNITS  16
#define KCH    64            // k-chunk
#define NCHUNK 16            // 1024 / 64
#define NBUF   4

#define WS_STR 72            // fp16 elems per W_s row (64 + 8 pad) -> 144B
#define AS_STR 72            // fp16 elems per A_s row (64 + 8 pad) -> 144B

// smem layout (bytes)
#define OFF_W    0
#define W_BYTES  (Hh * WS_STR * 2)            // 147456
#define A_BYTES  (BH * AS_STR * 2)            // 18432
#define OFF_A    (OFF_W + W_BYTES)            // 147456 ; 4 bufs -> 73728
#define OFF_WX   (OFF_A + NBUF * A_BYTES)     // 221184  (4*16 floats)
#define OFF_BIA  (OFF_WX + 256)               // 221440
#define OFF_WPH  (OFF_BIA + 256)              // 221696  (16*10 floats)
#define SMEM_BYTES (OFF_WPH + 640)            // 222336

// pre_s / hs reuse the A buffers during the epilogue (all mma done by then)
#define OFF_PRE  OFF_A                        // 128*66*4 = 33792 bytes
#define OFF_HS   (OFF_A + 34816)              // 128*16*4 = 8192 bytes

// ---------------- persistent device state ----------------
__device__ __align__(128) __half g_hbuf[2][BBat * Hh];
__device__ __align__(128) float  g_xT[SQ * BBat];     // transposed x: [t][b]
__device__ unsigned g_count = 0;
__device__ unsigned g_sense = 0;
__device__ unsigned g_wrc[32] = {};     // [half][16 groups]: 4 producers each, +4/step
__device__ unsigned g_rd[2] = {0, 0};   // per-half reader step counters (64/step)

// ---------------- small helpers ----------------
__device__ __forceinline__ unsigned ld_acq(const unsigned* p) {
    unsigned v;
    asm volatile("ld.acquire.gpu.global.u32 %0, [%1];" : "=r"(v) : "l"(p));
    return v;
}
__device__ __forceinline__ void st_rel(unsigned* p, unsigned v) {
    asm volatile("st.release.gpu.global.u32 [%0], %1;" :: "l"(p), "r"(v));
}
__device__ __forceinline__ void pollge(const unsigned* p, unsigned tgt) {
    if (ld_acq(p) >= tgt) return;
    while (ld_acq(p) < tgt) { __nanosleep(64); }
}

// full-grid sense-reversing barrier (init + final only)
__device__ __forceinline__ void gsync(unsigned& ls) {
    unsigned t = ls ^ 1u;
    __syncthreads();
    if (threadIdx.x == 0) {
        __threadfence();
        if (atomicAdd(&g_count, 1u) == NCTA - 1) { g_count = 0; st_rel(&g_sense, t); }
        else { while (ld_acq(&g_sense) != t) { __nanosleep(32); } }
    }
    __syncthreads();
    ls = t;
}

__device__ __forceinline__ void cpa16(uint32_t d, const void* s) {
    asm volatile("cp.async.cg.shared.global [%0], [%1], 16;" :: "r"(d), "l"(s));
}
#define CP_COMMIT() asm volatile("cp.async.commit_group;")
#define CP_WAIT(n)  asm volatile("cp.async.wait_group %0;" :: "n"(n))

__device__ __forceinline__ void ldsm4(uint32_t* r, uint32_t a) {
    asm volatile("ldmatrix.sync.aligned.m8n8.x4.shared.b16 {%0,%1,%2,%3}, [%4];"
                 : "=r"(r[0]), "=r"(r[1]), "=r"(r[2]), "=r"(r[3]) : "r"(a));
}
__device__ __forceinline__ void ldsm4t(uint32_t* r, uint32_t a) {
    asm volatile("ldmatrix.sync.aligned.m8n8.x4.trans.shared.b16 {%0,%1,%2,%3}, [%4];"
                 : "=r"(r[0]), "=r"(r[1]), "=r"(r[2]), "=r"(r[3]) : "r"(a));
}
__device__ __forceinline__ void mma16816(float* c, const uint32_t* a, const uint32_t* b) {
    asm volatile("mma.sync.aligned.m16n8k16.row.col.f32.f16.f16.f32 "
                 "{%0,%1,%2,%3}, {%4,%5,%6,%7}, {%8,%9}, {%0,%1,%2,%3};"
                 : "+f"(c[0]), "+f"(c[1]), "+f"(c[2]), "+f"(c[3])
                 : "r"(a[0]), "r"(a[1]), "r"(a[2]), "r"(a[3]), "r"(b[0]), "r"(b[1]));
}

__device__ __forceinline__ float tanh_ap(float z) {
    float r;
    asm("tanh.approx.f32 %0, %1;" : "=f"(r) : "f"(z));
    return r;
}
__device__ __forceinline__ float sig_ap(float z) {
    return fmaf(tanh_ap(z * 0.5f), 0.5f, 0.5f);
}

// issue one 128x64 fp16 k-chunk of h into an A buffer (4 cp.async/thread)
__device__ __forceinline__ void issue_chunk(uint32_t dbase, const __half* src, int tid) {
#pragma unroll
    for (int e = 0; e < 4; ++e) {
        int flat = tid + e * TPB;          // 0..1023
        int row  = flat >> 3;              // 0..127
        int seg  = flat & 7;               // 0..7  (16B segments)
        cpa16(dbase + row * (AS_STR * 2) + seg * 16, src + row * Hh + seg * 8);
    }
    CP_COMMIT();
}

// ---------------- the persistent LSTM kernel ----------------
__global__ void __launch_bounds__(TPB, 1) lstm_persistent_kernel(
    const float* __restrict__ x,
    const float* __restrict__ wgx, const float* __restrict__ wix,
    const float* __restrict__ wfx, const float* __restrict__ wox,
    const float* __restrict__ wgh, const float* __restrict__ wih,
    const float* __restrict__ wfh, const float* __restrict__ woh,
    const float* __restrict__ wph,
    const float* __restrict__ bg,  const float* __restrict__ bi,
    const float* __restrict__ bf_, const float* __restrict__ bo,
    const float* __restrict__ bp,
    float* __restrict__ out)
{
    extern __shared__ char smem[];
    const int tid  = threadIdx.x;
    const int bid  = blockIdx.x;
    const int lane = tid & 31;
    const int warp = tid >> 5;

    const int col_tile = bid & 63;        // hidden slice index
    const int b_half   = bid >> 6;        // batch half
    const int j0h      = col_tile * UNITS;
    const int rowbase  = b_half * BH;
    const int my_group = col_tile >> 2;   // which k-chunk my h columns feed

    __half* Ws   = (__half*)(smem + OFF_W);
    float* w_x_s = (float*)(smem + OFF_WX);
    float* b_s   = (float*)(smem + OFF_BIA);
    float* wph_s = (float*)(smem + OFF_WPH);
    float* pre_s = (float*)(smem + OFF_PRE);     // [128][66] fp32
    float* hs    = (float*)(smem + OFF_HS);      // [128][16] fp32

    const uint32_t smem_u = (uint32_t)__cvta_generic_to_shared(smem);

    // ---- init: convert weight slice fp32 -> fp16 into SMEM ----
    {
        const float* wh[4] = { wgh, wih, wfh, woh };
        for (int idx = tid; idx < Hh * NCOLS; idx += TPB) {
            int k = idx & (Hh - 1);
            int n = idx >> 10;             // 0..63
            int g = n >> 4;
            int u = n & 15;
            Ws[k * WS_STR + n] = __float2half_rn(wh[g][(j0h + u) * Hh + k]);
        }
        const float* wxp[4] = { wgx, wix, wfx, wox };
        const float* bv[4]  = { bg, bi, bf_, bo };
        if (tid < 64) {
            int g = tid >> 4, u = tid & 15;
            w_x_s[tid] = wxp[g][j0h + u];
            b_s[tid]   = bv[g][j0h + u];
        }
        if (tid < UNITS * CCls) {
            int u = tid / CCls, cl = tid % CCls;
            wph_s[tid] = wph[cl * Hh + j0h + u];
        }
    }

    // ---- zero h buffer 0, transpose x, init out = b_p ----
    {
        uint32_t* p = (uint32_t*)g_hbuf[0];
        int g = bid * TPB + tid;
        for (int w = g; w < (BBat * Hh * 2) / 4; w += NCTA * TPB) p[w] = 0u;
        for (int i = g; i < BBat * SQ; i += NCTA * TPB) {
            int b  = i >> 9;               // /SQ
            int tt = i & (SQ - 1);
            g_xT[tt * BBat + b] = x[i];    // coalesced read, scattered write (one-time)
        }
        if (bid == 0) {
            for (int i = tid; i < BBat * CCls; i += TPB) out[i] = bp[i % CCls];
        }
    }

    unsigned ls = 0;
    gsync(ls);   // barrier #1 (covers init)

    // per-thread epilogue constants
    const int u_e  = tid & 15;          // unit
    const int rg_e = tid >> 4;          // row group 0..15
    float wxu[4], bu[4];
#pragma unroll
    for (int g = 0; g < 4; ++g) { wxu[g] = w_x_s[g * 16 + u_e]; bu[g] = b_s[g * 16 + u_e]; }

    // per-thread mma tile constants
    const int wm = (warp >> 1) * 32;
    const int wn = (warp & 1) * 32;
    const uint32_t a_byte = (uint32_t)(((wm + (lane & 15)) * AS_STR + (lane >> 4) * 8) * 2);
    const uint32_t w_byte = (uint32_t)(((lane & 15) * WS_STR + wn + (lane >> 4) * 8) * 2);

    const unsigned* wflags = &g_wrc[b_half * 16];

    float cst[8];
#pragma unroll
    for (int q = 0; q < 8; ++q) cst[q] = 0.0f;

    for (int t = 0; t < SQ; ++t) {
        const __half* hsrc = g_hbuf[t & 1] + (size_t)rowbase * Hh;
        __half* hdst = g_hbuf[(t + 1) & 1];
        const unsigned wtgt = 4u * (unsigned)t;   // group flag target for step t

        float acc[2][4][4];
#pragma unroll
        for (int a = 0; a < 2; ++a)
#pragma unroll
            for (int b = 0; b < 4; ++b)
#pragma unroll
                for (int e = 0; e < 4; ++e) acc[a][b][e] = 0.0f;

        // prologue: gate groups 0-2 with 3 quiet pollers, then fill 3 stages
        if (tid < 3) pollge(&wflags[tid], wtgt);
        __syncthreads();
        issue_chunk(smem_u + OFF_A + 0 * A_BYTES, hsrc + 0 * KCH, tid);
        issue_chunk(smem_u + OFF_A + 1 * A_BYTES, hsrc + 1 * KCH, tid);
        issue_chunk(smem_u + OFF_A + 2 * A_BYTES, hsrc + 2 * KCH, tid);

#pragma unroll
        for (int c = 0; c < NCHUNK; ++c) {
            if (c < NCHUNK - 2)      { CP_WAIT(2); }
            else if (c == NCHUNK - 2){ CP_WAIT(1); }
            else                     { CP_WAIT(0); }
            // single quiet poller gates the chunk about to be issued;
            // joins the CTA at the barrier below (no extra barrier).
            if (tid == 0 && c + 3 < NCHUNK) pollge(&wflags[c + 3], wtgt);
            __syncthreads();
            if (c == NCHUNK - 1) {
                // all gmem reads of this step's h complete (all threads waited + sync)
                if (tid == 0) { __threadfence(); atomicAdd(&g_rd[b_half], 1u); }
            }
            if (c + 3 < NCHUNK) {
                issue_chunk(smem_u + OFF_A + ((c + 3) & 3) * A_BYTES,
                            hsrc + (c + 3) * KCH, tid);
            }

            const uint32_t abase = smem_u + OFF_A + (uint32_t)((c & 3) * A_BYTES) + a_byte;
            const uint32_t wbase = smem_u + OFF_W + w_byte + (uint32_t)(c * (KCH * WS_STR * 2));
#pragma unroll
            for (int kk = 0; kk < 4; ++kk) {
                uint32_t ka = abase + kk * 16 * 2;
                uint32_t kw = wbase + (uint32_t)(kk * 16 * WS_STR * 2);
                uint32_t a0[4], a1[4], b0[4], b1[4];
                ldsm4(a0, ka);
                ldsm4(a1, ka + 16 * AS_STR * 2);
                ldsm4t(b0, kw);
                ldsm4t(b1, kw + 16 * 2);
                mma16816(acc[0][0], a0, b0 + 0);
                mma16816(acc[0][1], a0, b0 + 2);
                mma16816(acc[0][2], a0, b1 + 0);
                mma16816(acc[0][3], a0, b1 + 2);
                mma16816(acc[1][0], a1, b0 + 0);
                mma16816(acc[1][1], a1, b0 + 2);
                mma16816(acc[1][2], a1, b1 + 0);
                mma16816(acc[1][3], a1, b1 + 2);
            }
        }
        __syncthreads();    // all mma done before pre_s overwrites A buffers

        // ---- store pre-activations to smem (fp32, padded stride 66) ----
#pragma unroll
        for (int mi = 0; mi < 2; ++mi) {
#pragma unroll
            for (int nj = 0; nj < 4; ++nj) {
                int r0 = wm + mi * 16 + (lane >> 2);
                int cb = wn + nj * 8 + (lane & 3) * 2;
                *(float2*)&pre_s[r0 * 66 + cb]       = make_float2(acc[mi][nj][0], acc[mi][nj][1]);
                *(float2*)&pre_s[(r0 + 8) * 66 + cb] = make_float2(acc[mi][nj][2], acc[mi][nj][3]);
            }
        }
        __syncthreads();

        // readers of the buffer we are about to overwrite (step t-1) must be done
        pollge(&g_rd[b_half], 64u * (unsigned)t);

        // ---- gates, cell update, h write ----
        const bool last = (t == SQ - 1);
        const float4* xp = (const float4*)(g_xT + (size_t)t * BBat + rowbase + rg_e * 8);
        float4 xa = xp[0];
        float4 xb = xp[1];
        float xv[8] = { xa.x, xa.y, xa.z, xa.w, xb.x, xb.y, xb.z, xb.w };
#pragma unroll
        for (int q = 0; q < 8; ++q) {
            int r = rg_e * 8 + q;
            const float* pr = &pre_s[r * 66 + u_e];
            float zg = pr[0]  + xv[q] * wxu[0] + bu[0];
            float zi = pr[16] + xv[q] * wxu[1] + bu[1];
            float zf = pr[32] + xv[q] * wxu[2] + bu[2];
            float zo = pr[48] + xv[q] * wxu[3] + bu[3];
            float gg = tanh_ap(zg);
            float ii = sig_ap(zi);
            float ff = sig_ap(zf);
            float oo = sig_ap(zo);
            float cn = gg * ii + cst[q] * ff;
            cst[q] = cn;
            float hh = tanh_ap(cn) * oo;
            hdst[(size_t)(rowbase + r) * Hh + j0h + u_e] = __float2half_rn(hh);
            if (last) hs[r * UNITS + u_e] = hh;
        }

        if (last) {
            __syncthreads();
            if (tid < BH) {
                int r = tid;
                float s[CCls];
#pragma unroll
                for (int cl = 0; cl < CCls; ++cl) s[cl] = 0.0f;
#pragma unroll
                for (int u2 = 0; u2 < UNITS; ++u2) {
                    float hv = hs[r * UNITS + u2];
#pragma unroll
                    for (int cl = 0; cl < CCls; ++cl) s[cl] += hv * wph_s[u2 * CCls + cl];
                }
#pragma unroll
                for (int cl = 0; cl < CCls; ++cl)
                    atomicAdd(&out[(rowbase + r) * CCls + cl], s[cl]);
            }
        }

        // publish step-t h for my producer group
        __syncthreads();
        if (tid == 0) { __threadfence(); atomicAdd(&g_wrc[b_half * 16 + my_group], 1u); }
    }

    // final full barrier, then reset monotonic counters for the next graph replay
    gsync(ls);   // barrier #2 (even count -> g_sense back to 0)
    if (bid == 0 && tid == 0) {
#pragma unroll
        for (int j = 0; j < 32; ++j) g_wrc[j] = 0;
        g_rd[0] = 0; g_rd[1] = 0;
        __threadfence();
    }
}

// ---------------- launch ----------------
extern "C" void kernel_launch(void* const* d_in, const int* in_sizes, int n_in,
                              void* d_out, int out_size)
{
    const float* x   = (const float*)d_in[0];
    const float* wgx = (const float*)d_in[1];
    const float* wix = (const float*)d_in[2];
    const float* wfx = (const float*)d_in[3];
    const float* wox = (const float*)d_in[4];
    const float* wgh = (const float*)d_in[5];
    const float* wih = (const float*)d_in[6];
    const float* wfh = (const float*)d_in[7];
    const float* woh = (const float*)d_in[8];
    const float* wph = (const float*)d_in[9];
    const float* bg  = (const float*)d_in[10];
    const float* bi  = (const float*)d_in[11];
    const float* bf_ = (const float*)d_in[12];
    const float* bo  = (const float*)d_in[13];
    const float* bp  = (const float*)d_in[14];
    float* out = (float*)d_out;

    cudaFuncSetAttribute(lstm_persistent_kernel,
                         cudaFuncAttributeMaxDynamicSharedMemorySize, SMEM_BYTES);

    lstm_persistent_kernel<<<NCTA, TPB, SMEM_BYTES>>>(
        x, wgx, wix, wfx, wox, wgh, wih, wfh, woh, wph,
        bg, bi, bf_, bo, bp, out);
}

// round 13
// speedup vs baseline: 1.3507x; 1.3507x over previous
#include <cuda_runtime.h>
#include <cuda_fp16.h>
#include <cstdint>

// ---------------- problem constants ----------------
#define Hh   1024
#define SQ   512
#define BBat 256
#define CCls 10

// ---------------- kernel config ----------------
#define NCTA   128
#define TPB    256
#define BH     128           // batch rows per CTA
#define NCOLS  64            // 16 hidden units * 4 gates
#define UNITS  16
#define KCH    64            // k-chunk
#define NCHUNK 16            // 1024 / 64
#define NBUF   4

#define WS_STR 72            // fp16 elems per W_s row (64 + 8 pad) -> 144B
#define AS_STR 72            // fp16 elems per A_s row (64 + 8 pad) -> 144B

// smem layout (bytes)
#define OFF_W    0
#define W_BYTES  (Hh * WS_STR * 2)            // 147456
#define A_BYTES  (BH * AS_STR * 2)            // 18432
#define OFF_A    (OFF_W + W_BYTES)            // 147456 ; 4 bufs -> 73728
#define OFF_WX   (OFF_A + NBUF * A_BYTES)     // 221184  (4*16 floats)
#define OFF_BIA  (OFF_WX + 256)               // 221440
#define OFF_WPH  (OFF_BIA + 256)              // 221696  (16*10 floats)
#define SMEM_BYTES (OFF_WPH + 640)            // 222336

// hs reuses A buffer space during the final projection (chunk loop done)
#define OFF_HS   OFF_A                        // 128*16*4 = 8192 bytes

// ---------------- persistent device state ----------------
__device__ __align__(128) __half g_hbuf[2][BBat * Hh];
__device__ __align__(128) float  g_xT[SQ * BBat];     // transposed x: [t][b]
__device__ unsigned g_count = 0;
__device__ unsigned g_sense = 0;
__device__ unsigned g_wrc[16] = {};   // [half][8]: 8 producers each, +1/step
__device__ unsigned g_rdc[16] = {};   // [half][8]: 8 readers each, +1/step

// ---------------- small helpers ----------------
__device__ __forceinline__ unsigned ld_acq(const unsigned* p) {
    unsigned v;
    asm volatile("ld.acquire.gpu.global.u32 %0, [%1];" : "=r"(v) : "l"(p));
    return v;
}
__device__ __forceinline__ void st_rel(unsigned* p, unsigned v) {
    asm volatile("st.release.gpu.global.u32 [%0], %1;" :: "l"(p), "r"(v));
}
__device__ __forceinline__ void pollge(const unsigned* p, unsigned tgt) {
    if (ld_acq(p) >= tgt) return;
    while (ld_acq(p) < tgt) { __nanosleep(64); }
}

// full-grid sense-reversing barrier (init + final only)
__device__ __forceinline__ void gsync(unsigned& ls) {
    unsigned t = ls ^ 1u;
    __syncthreads();
    if (threadIdx.x == 0) {
        __threadfence();
        if (atomicAdd(&g_count, 1u) == NCTA - 1) { g_count = 0; st_rel(&g_sense, t); }
        else { while (ld_acq(&g_sense) != t) { __nanosleep(32); } }
    }
    __syncthreads();
    ls = t;
}

__device__ __forceinline__ void cpa16(uint32_t d, const void* s) {
    asm volatile("cp.async.cg.shared.global [%0], [%1], 16;" :: "r"(d), "l"(s));
}
#define CP_COMMIT() asm volatile("cp.async.commit_group;")
#define CP_WAIT(n)  asm volatile("cp.async.wait_group %0;" :: "n"(n))

__device__ __forceinline__ void ldsm4(uint32_t* r, uint32_t a) {
    asm volatile("ldmatrix.sync.aligned.m8n8.x4.shared.b16 {%0,%1,%2,%3}, [%4];"
                 : "=r"(r[0]), "=r"(r[1]), "=r"(r[2]), "=r"(r[3]) : "r"(a));
}
__device__ __forceinline__ void ldsm4t(uint32_t* r, uint32_t a) {
    asm volatile("ldmatrix.sync.aligned.m8n8.x4.trans.shared.b16 {%0,%1,%2,%3}, [%4];"
                 : "=r"(r[0]), "=r"(r[1]), "=r"(r[2]), "=r"(r[3]) : "r"(a));
}
__device__ __forceinline__ void mma16816(float* c, const uint32_t* a, const uint32_t* b) {
    asm volatile("mma.sync.aligned.m16n8k16.row.col.f32.f16.f16.f32 "
                 "{%0,%1,%2,%3}, {%4,%5,%6,%7}, {%8,%9}, {%0,%1,%2,%3};"
                 : "+f"(c[0]), "+f"(c[1]), "+f"(c[2]), "+f"(c[3])
                 : "r"(a[0]), "r"(a[1]), "r"(a[2]), "r"(a[3]), "r"(b[0]), "r"(b[1]));
}

__device__ __forceinline__ float tanh_ap(float z) {
    float r;
    asm("tanh.approx.f32 %0, %1;" : "=f"(r) : "f"(z));
    return r;
}
__device__ __forceinline__ float sig_ap(float z) {
    return fmaf(tanh_ap(z * 0.5f), 0.5f, 0.5f);
}

// warp-local: load THIS WARP's 16 rows of a 128x64 k-chunk (4 cpa16/lane)
__device__ __forceinline__ void issue_chunk_w(uint32_t dbase, const __half* src,
                                              int warp, int lane) {
#pragma unroll
    for (int e = 0; e < 4; ++e) {
        int task = lane + e * 32;          // 0..127
        int r16  = task >> 3;              // 0..15 row within warp tile
        int seg  = task & 7;               // 0..7  (16B segments)
        int row  = warp * 16 + r16;
        cpa16(dbase + row * (AS_STR * 2) + seg * 16, src + row * Hh + seg * 8);
    }
    CP_COMMIT();
}

// ---------------- the persistent LSTM kernel ----------------
__global__ void __launch_bounds__(TPB, 1) lstm_persistent_kernel(
    const float* __restrict__ x,
    const float* __restrict__ wgx, const float* __restrict__ wix,
    const float* __restrict__ wfx, const float* __restrict__ wox,
    const float* __restrict__ wgh, const float* __restrict__ wih,
    const float* __restrict__ wfh, const float* __restrict__ woh,
    const float* __restrict__ wph,
    const float* __restrict__ bg,  const float* __restrict__ bi,
    const float* __restrict__ bf_, const float* __restrict__ bo,
    const float* __restrict__ bp,
    float* __restrict__ out)
{
    extern __shared__ char smem[];
    const int tid  = threadIdx.x;
    const int bid  = blockIdx.x;
    const int lane = tid & 31;
    const int warp = tid >> 5;

    const int col_tile = bid & 63;        // hidden slice index
    const int b_half   = bid >> 6;        // batch half
    const int j0h      = col_tile * UNITS;
    const int rowbase  = b_half * BH;

    __half* Ws   = (__half*)(smem + OFF_W);
    float* w_x_s = (float*)(smem + OFF_WX);
    float* b_s   = (float*)(smem + OFF_BIA);
    float* wph_s = (float*)(smem + OFF_WPH);
    float* hs    = (float*)(smem + OFF_HS);      // [128][16] fp32 (final step only)

    const uint32_t smem_u = (uint32_t)__cvta_generic_to_shared(smem);

    // ---- init: convert weight slice fp32 -> fp16 into SMEM ----
    {
        const float* wh[4] = { wgh, wih, wfh, woh };
        for (int idx = tid; idx < Hh * NCOLS; idx += TPB) {
            int k = idx & (Hh - 1);
            int n = idx >> 10;             // 0..63
            int g = n >> 4;
            int u = n & 15;
            Ws[k * WS_STR + n] = __float2half_rn(wh[g][(j0h + u) * Hh + k]);
        }
        const float* wxp[4] = { wgx, wix, wfx, wox };
        const float* bv[4]  = { bg, bi, bf_, bo };
        if (tid < 64) {
            int g = tid >> 4, u = tid & 15;
            w_x_s[tid] = wxp[g][j0h + u];
            b_s[tid]   = bv[g][j0h + u];
        }
        if (tid < UNITS * CCls) {
            int u = tid / CCls, cl = tid % CCls;
            wph_s[tid] = wph[cl * Hh + j0h + u];
        }
    }

    // ---- zero h buffer 0, transpose x, init out = b_p ----
    {
        uint32_t* p = (uint32_t*)g_hbuf[0];
        int g = bid * TPB + tid;
        for (int w = g; w < (BBat * Hh * 2) / 4; w += NCTA * TPB) p[w] = 0u;
        for (int i = g; i < BBat * SQ; i += NCTA * TPB) {
            int b  = i >> 9;               // /SQ
            int tt = i & (SQ - 1);
            g_xT[tt * BBat + b] = x[i];
        }
        if (bid == 0) {
            for (int i = tid; i < BBat * CCls; i += TPB) out[i] = bp[i % CCls];
        }
    }

    unsigned ls = 0;
    gsync(ls);   // barrier #1 (covers init)

    // ---- per-thread constants ----
    const int a_  = lane & 3;                       // unit residue
    const int r0_ = warp * 16 + (lane >> 2);        // my row (half 0); +8 for half 1
    // my 4 units: {2a, 2a+1, 2a+8, 2a+9}
    int ulist[4] = { 2 * a_, 2 * a_ + 1, 2 * a_ + 8, 2 * a_ + 9 };
    // x-weight / bias per [gate][uu]
    float wxr[4][4], brr[4][4];
#pragma unroll
    for (int g = 0; g < 4; ++g)
#pragma unroll
        for (int uu = 0; uu < 4; ++uu) {
            wxr[g][uu] = w_x_s[g * 16 + ulist[uu]];
            brr[g][uu] = b_s[g * 16 + ulist[uu]];
        }

    // mma smem addresses
    const uint32_t a_byte = (uint32_t)(((warp * 16 + (lane & 15)) * AS_STR + (lane >> 4) * 8) * 2);
    const uint32_t w_byte = (uint32_t)(((lane & 15) * WS_STR + (lane >> 4) * 8) * 2);

    float cst[2][4];
#pragma unroll
    for (int m = 0; m < 2; ++m)
#pragma unroll
        for (int uu = 0; uu < 4; ++uu) cst[m][uu] = 0.0f;

    for (int t = 0; t < SQ; ++t) {
        const __half* hsrc = g_hbuf[t & 1] + (size_t)rowbase * Hh;
        __half* hdst = g_hbuf[(t + 1) & 1];

        // wait: all 64 producers of my half published step t-1 (8 quiet pollers)
        if (tid < 8) pollge(&g_wrc[b_half * 8 + tid], 8u * (unsigned)t);
        __syncthreads();

        float acc[8][4];
#pragma unroll
        for (int nf = 0; nf < 8; ++nf)
#pragma unroll
            for (int e = 0; e < 4; ++e) acc[nf][e] = 0.0f;

        // warp-private pipeline: fill 3 stages (own 16 rows only)
        issue_chunk_w(smem_u + OFF_A + 0 * A_BYTES, hsrc + 0 * KCH, warp, lane);
        issue_chunk_w(smem_u + OFF_A + 1 * A_BYTES, hsrc + 1 * KCH, warp, lane);
        issue_chunk_w(smem_u + OFF_A + 2 * A_BYTES, hsrc + 2 * KCH, warp, lane);

        // ---- 16-chunk GEMM, NO CTA barriers: each warp fully independent ----
#pragma unroll
        for (int c = 0; c < NCHUNK; ++c) {
            if (c + 3 < NCHUNK)
                issue_chunk_w(smem_u + OFF_A + ((c + 3) & 3) * A_BYTES,
                              hsrc + (c + 3) * KCH, warp, lane);
            if (c < NCHUNK - 3)      { CP_WAIT(3); }
            else if (c == NCHUNK - 3){ CP_WAIT(2); }
            else if (c == NCHUNK - 2){ CP_WAIT(1); }
            else                     { CP_WAIT(0); }

            const uint32_t abase = smem_u + OFF_A + (uint32_t)((c & 3) * A_BYTES) + a_byte;
            const uint32_t wbase = smem_u + OFF_W + w_byte + (uint32_t)(c * (KCH * WS_STR * 2));
#pragma unroll
            for (int kk = 0; kk < 4; ++kk) {
                uint32_t av[4];
                ldsm4(av, abase + kk * 16 * 2);
                const uint32_t kw = wbase + (uint32_t)(kk * 16 * WS_STR * 2);
#pragma unroll
                for (int j = 0; j < 4; ++j) {
                    uint32_t bv4[4];
                    ldsm4t(bv4, kw + j * 16 * 2);
                    mma16816(acc[2 * j],     av, bv4 + 0);
                    mma16816(acc[2 * j + 1], av, bv4 + 2);
                }
            }
        }

        // all warps finished their gmem reads of hsrc (own wait_group done)
        __syncthreads();
        if (tid == 0) { __threadfence(); atomicAdd(&g_rdc[b_half * 8 + (col_tile & 7)], 1u); }

        // readers of the buffer we are about to overwrite (step t-1) must be done
        if (tid < 8) pollge(&g_rdc[b_half * 8 + tid], 8u * (unsigned)t);
        __syncthreads();

        // ---- epilogue: fully in registers ----
        const bool last = (t == SQ - 1);
#pragma unroll
        for (int m = 0; m < 2; ++m) {
            const int r = r0_ + 8 * m;
            const float xv = g_xT[t * BBat + rowbase + r];
            float hv[4];
#pragma unroll
            for (int uu = 0; uu < 4; ++uu) {
                const int nfb = uu >> 1;           // u>>3
                const int e   = 2 * m + (uu & 1);  // frag elem
                float zg = acc[0 + nfb][e] + xv * wxr[0][uu] + brr[0][uu];
                float zi = acc[2 + nfb][e] + xv * wxr[1][uu] + brr[1][uu];
                float zf = acc[4 + nfb][e] + xv * wxr[2][uu] + brr[2][uu];
                float zo = acc[6 + nfb][e] + xv * wxr[3][uu] + brr[3][uu];
                float gg = tanh_ap(zg);
                float ii = sig_ap(zi);
                float ff = sig_ap(zf);
                float oo = sig_ap(zo);
                float cn = gg * ii + cst[m][uu] * ff;
                cst[m][uu] = cn;
                hv[uu] = tanh_ap(cn) * oo;
                if (last) hs[r * UNITS + ulist[uu]] = hv[uu];
            }
            __half* hp = &hdst[(size_t)(rowbase + r) * Hh + j0h];
            *(__half2*)&hp[2 * a_]     = __floats2half2_rn(hv[0], hv[1]);
            *(__half2*)&hp[2 * a_ + 8] = __floats2half2_rn(hv[2], hv[3]);
        }

        if (last) {
            __syncthreads();
            if (tid < BH) {
                int r = tid;
                float s[CCls];
#pragma unroll
                for (int cl = 0; cl < CCls; ++cl) s[cl] = 0.0f;
#pragma unroll
                for (int u2 = 0; u2 < UNITS; ++u2) {
                    float hvv = hs[r * UNITS + u2];
#pragma unroll
                    for (int cl = 0; cl < CCls; ++cl) s[cl] += hvv * wph_s[u2 * CCls + cl];
                }
#pragma unroll
                for (int cl = 0; cl < CCls; ++cl)
                    atomicAdd(&out[(rowbase + r) * CCls + cl], s[cl]);
            }
        }

        // publish step-t h for my half
        __syncthreads();
        if (tid == 0) { __threadfence(); atomicAdd(&g_wrc[b_half * 8 + (col_tile & 7)], 1u); }
    }

    // final full barrier, then reset monotonic counters for the next graph replay
    gsync(ls);   // barrier #2 (even count -> g_sense back to 0)
    if (bid == 0 && tid == 0) {
#pragma unroll
        for (int j = 0; j < 16; ++j) { g_wrc[j] = 0; g_rdc[j] = 0; }
        __threadfence();
    }
}

// ---------------- launch ----------------
extern "C" void kernel_launch(void* const* d_in, const int* in_sizes, int n_in,
                              void* d_out, int out_size)
{
    const float* x   = (const float*)d_in[0];
    const float* wgx = (const float*)d_in[1];
    const float* wix = (const float*)d_in[2];
    const float* wfx = (const float*)d_in[3];
    const float* wox = (const float*)d_in[4];
    const float* wgh = (const float*)d_in[5];
    const float* wih = (const float*)d_in[6];
    const float* wfh = (const float*)d_in[7];
    const float* woh = (const float*)d_in[8];
    const float* wph = (const float*)d_in[9];
    const float* bg  = (const float*)d_in[10];
    const float* bi  = (const float*)d_in[11];
    const float* bf_ = (const float*)d_in[12];
    const float* bo  = (const float*)d_in[13];
    const float* bp  = (const float*)d_in[14];
    float* out = (float*)d_out;

    cudaFuncSetAttribute(lstm_persistent_kernel,
                         cudaFuncAttributeMaxDynamicSharedMemorySize, SMEM_BYTES);

    lstm_persistent_kernel<<<NCTA, TPB, SMEM_BYTES>>>(
        x, wgx, wix, wfx, wox, wgh, wih, wfh, woh, wph,
        bg, bi, bf_, bo, bp, out);
}

// round 17
// speedup vs baseline: 1.5767x; 1.1673x over previous
#include <cuda_runtime.h>
#include <cuda_fp16.h>
#include <cstdint>

// ---------------- problem constants ----------------
#define Hh   1024
#define SQ   512
#define BBat 256
#define CCls 10

// ---------------- kernel config ----------------
#define NCTA   128
#define TPB    256
#define BH     128           // batch rows per CTA
#define NCOLS  64            // 16 hidden units * 4 gates
#define UNITS  16
#define KCH    64            // k-chunk
#define NCHUNK 16            // 1024 / 64
#define NBUF   4

#define WS_STR 72            // fp16 elems per W_s row (64 + 8 pad) -> 144B
#define AS_STR 72            // fp16 elems per A_s row (64 + 8 pad) -> 144B

// smem layout (bytes)
#define OFF_W    0
#define W_BYTES  (Hh * WS_STR * 2)            // 147456
#define A_BYTES  (BH * AS_STR * 2)            // 18432
#define OFF_A    (OFF_W + W_BYTES)            // 147456 ; 4 bufs -> 73728
#define OFF_WX   (OFF_A + NBUF * A_BYTES)     // 221184  (4*16 floats)
#define OFF_BIA  (OFF_WX + 256)               // 221440
#define OFF_WPH  (OFF_BIA + 256)              // 221696  (16*10 floats)
#define SMEM_BYTES (OFF_WPH + 640)            // 222336

// hs reuses A buffer space during the final projection (guarded by barrier)
#define OFF_HS   OFF_A                        // 128*16*4 = 8192 bytes

// ---------------- persistent device state ----------------
// TRIPLE-buffered h: source = t%3, dest = (t+1)%3. The producer-wait at step
// start implies all CTAs finished step t-1, hence finished READING buffer
// (t+1)%3 (its last use as source was step t-2) -> no reader-done counters.
__device__ __align__(128) __half g_hbuf[3][BBat * Hh];
__device__ __align__(128) float  g_xT[SQ * BBat];     // transposed x: [t][b]
__device__ unsigned g_count = 0;
__device__ unsigned g_sense = 0;
__device__ unsigned g_wrc[16] = {};   // [half][8]: 8 producers each, +1/step

// ---------------- small helpers ----------------
__device__ __forceinline__ unsigned ld_acq(const unsigned* p) {
    unsigned v;
    asm volatile("ld.acquire.gpu.global.u32 %0, [%1];" : "=r"(v) : "l"(p));
    return v;
}
__device__ __forceinline__ void st_rel(unsigned* p, unsigned v) {
    asm volatile("st.release.gpu.global.u32 [%0], %1;" :: "l"(p), "r"(v));
}
__device__ __forceinline__ void pollge(const unsigned* p, unsigned tgt) {
    if (ld_acq(p) >= tgt) return;
    while (ld_acq(p) < tgt) { __nanosleep(64); }
}

// full-grid sense-reversing barrier (init + final only)
__device__ __forceinline__ void gsync(unsigned& ls) {
    unsigned t = ls ^ 1u;
    __syncthreads();
    if (threadIdx.x == 0) {
        __threadfence();
        if (atomicAdd(&g_count, 1u) == NCTA - 1) { g_count = 0; st_rel(&g_sense, t); }
        else { while (ld_acq(&g_sense) != t) { __nanosleep(32); } }
    }
    __syncthreads();
    ls = t;
}

__device__ __forceinline__ void cpa16(uint32_t d, const void* s) {
    asm volatile("cp.async.cg.shared.global [%0], [%1], 16;" :: "r"(d), "l"(s));
}
#define CP_COMMIT() asm volatile("cp.async.commit_group;")
#define CP_WAIT(n)  asm volatile("cp.async.wait_group %0;" :: "n"(n))

__device__ __forceinline__ void ldsm4(uint32_t* r, uint32_t a) {
    asm volatile("ldmatrix.sync.aligned.m8n8.x4.shared.b16 {%0,%1,%2,%3}, [%4];"
                 : "=r"(r[0]), "=r"(r[1]), "=r"(r[2]), "=r"(r[3]) : "r"(a));
}
__device__ __forceinline__ void ldsm4t(uint32_t* r, uint32_t a) {
    asm volatile("ldmatrix.sync.aligned.m8n8.x4.trans.shared.b16 {%0,%1,%2,%3}, [%4];"
                 : "=r"(r[0]), "=r"(r[1]), "=r"(r[2]), "=r"(r[3]) : "r"(a));
}
__device__ __forceinline__ void mma16816(float* c, const uint32_t* a, const uint32_t* b) {
    asm volatile("mma.sync.aligned.m16n8k16.row.col.f32.f16.f16.f32 "
                 "{%0,%1,%2,%3}, {%4,%5,%6,%7}, {%8,%9}, {%0,%1,%2,%3};"
                 : "+f"(c[0]), "+f"(c[1]), "+f"(c[2]), "+f"(c[3])
                 : "r"(a[0]), "r"(a[1]), "r"(a[2]), "r"(a[3]), "r"(b[0]), "r"(b[1]));
}

__device__ __forceinline__ float tanh_ap(float z) {
    float r;
    asm("tanh.approx.f32 %0, %1;" : "=f"(r) : "f"(z));
    return r;
}
__device__ __forceinline__ float sig_ap(float z) {
    return fmaf(tanh_ap(z * 0.5f), 0.5f, 0.5f);
}

// warp-local: load THIS WARP's 16 rows of a 128x64 k-chunk (4 cpa16/lane)
__device__ __forceinline__ void issue_chunk_w(uint32_t dbase, const __half* src,
                                              int warp, int lane) {
#pragma unroll
    for (int e = 0; e < 4; ++e) {
        int task = lane + e * 32;          // 0..127
        int r16  = task >> 3;              // 0..15 row within warp tile
        int seg  = task & 7;               // 0..7  (16B segments)
        int row  = warp * 16 + r16;
        cpa16(dbase + row * (AS_STR * 2) + seg * 16, src + row * Hh + seg * 8);
    }
    CP_COMMIT();
}

// ---------------- the persistent LSTM kernel ----------------
__global__ void __launch_bounds__(TPB, 1) lstm_persistent_kernel(
    const float* __restrict__ x,
    const float* __restrict__ wgx, const float* __restrict__ wix,
    const float* __restrict__ wfx, const float* __restrict__ wox,
    const float* __restrict__ wgh, const float* __restrict__ wih,
    const float* __restrict__ wfh, const float* __restrict__ woh,
    const float* __restrict__ wph,
    const float* __restrict__ bg,  const float* __restrict__ bi,
    const float* __restrict__ bf_, const float* __restrict__ bo,
    const float* __restrict__ bp,
    float* __restrict__ out)
{
    extern __shared__ char smem[];
    const int tid  = threadIdx.x;
    const int bid  = blockIdx.x;
    const int lane = tid & 31;
    const int warp = tid >> 5;

    const int col_tile = bid & 63;        // hidden slice index
    const int b_half   = bid >> 6;        // batch half
    const int j0h      = col_tile * UNITS;
    const int rowbase  = b_half * BH;

    __half* Ws   = (__half*)(smem + OFF_W);
    float* w_x_s = (float*)(smem + OFF_WX);
    float* b_s   = (float*)(smem + OFF_BIA);
    float* wph_s = (float*)(smem + OFF_WPH);
    float* hs    = (float*)(smem + OFF_HS);      // [128][16] fp32 (final step only)

    const uint32_t smem_u = (uint32_t)__cvta_generic_to_shared(smem);

    // ---- init: convert weight slice fp32 -> fp16 into SMEM ----
    {
        const float* wh[4] = { wgh, wih, wfh, woh };
        for (int idx = tid; idx < Hh * NCOLS; idx += TPB) {
            int k = idx & (Hh - 1);
            int n = idx >> 10;             // 0..63
            int g = n >> 4;
            int u = n & 15;
            Ws[k * WS_STR + n] = __float2half_rn(wh[g][(j0h + u) * Hh + k]);
        }
        const float* wxp[4] = { wgx, wix, wfx, wox };
        const float* bv[4]  = { bg, bi, bf_, bo };
        if (tid < 64) {
            int g = tid >> 4, u = tid & 15;
            w_x_s[tid] = wxp[g][j0h + u];
            b_s[tid]   = bv[g][j0h + u];
        }
        if (tid < UNITS * CCls) {
            int u = tid / CCls, cl = tid % CCls;
            wph_s[tid] = wph[cl * Hh + j0h + u];
        }
    }

    // ---- zero h buffer 0, transpose x, init out = b_p ----
    {
        uint32_t* p = (uint32_t*)g_hbuf[0];
        int g = bid * TPB + tid;
        for (int w = g; w < (BBat * Hh * 2) / 4; w += NCTA * TPB) p[w] = 0u;
        for (int i = g; i < BBat * SQ; i += NCTA * TPB) {
            int b  = i >> 9;               // /SQ
            int tt = i & (SQ - 1);
            g_xT[tt * BBat + b] = x[i];
        }
        if (bid == 0) {
            for (int i = tid; i < BBat * CCls; i += TPB) out[i] = bp[i % CCls];
        }
    }

    unsigned ls = 0;
    gsync(ls);   // barrier #1 (covers init)

    // ---- per-thread constants ----
    const int a_  = lane & 3;                       // unit residue
    const int r0_ = warp * 16 + (lane >> 2);        // my row (half 0); +8 for half 1
    // my 4 units: {2a, 2a+1, 2a+8, 2a+9}
    int ulist[4] = { 2 * a_, 2 * a_ + 1, 2 * a_ + 8, 2 * a_ + 9 };
    float wxr[4][4], brr[4][4];
#pragma unroll
    for (int g = 0; g < 4; ++g)
#pragma unroll
        for (int uu = 0; uu < 4; ++uu) {
            wxr[g][uu] = w_x_s[g * 16 + ulist[uu]];
            brr[g][uu] = b_s[g * 16 + ulist[uu]];
        }

    // mma smem addresses
    const uint32_t a_byte = (uint32_t)(((warp * 16 + (lane & 15)) * AS_STR + (lane >> 4) * 8) * 2);
    const uint32_t w_byte = (uint32_t)(((lane & 15) * WS_STR + (lane >> 4) * 8) * 2);

    float cst[2][4];
#pragma unroll
    for (int m = 0; m < 2; ++m)
#pragma unroll
        for (int uu = 0; uu < 4; ++uu) cst[m][uu] = 0.0f;

    int src_idx = 0;                       // t % 3
    for (int t = 0; t < SQ; ++t) {
        const __half* hsrc = g_hbuf[src_idx] + (size_t)rowbase * Hh;
        int dst_idx = src_idx + 1; if (dst_idx == 3) dst_idx = 0;
        __half* hdst = g_hbuf[dst_idx];
        src_idx = dst_idx;

        // wait: all 64 producers of my half published step t-1 (8 quiet pollers)
        if (tid < 8) pollge(&g_wrc[b_half * 8 + tid], 8u * (unsigned)t);
        __syncthreads();

        float acc[8][4];
#pragma unroll
        for (int nf = 0; nf < 8; ++nf)
#pragma unroll
            for (int e = 0; e < 4; ++e) acc[nf][e] = 0.0f;

        // warp-private pipeline: fill 3 stages (own 16 rows only)
        issue_chunk_w(smem_u + OFF_A + 0 * A_BYTES, hsrc + 0 * KCH, warp, lane);
        issue_chunk_w(smem_u + OFF_A + 1 * A_BYTES, hsrc + 1 * KCH, warp, lane);
        issue_chunk_w(smem_u + OFF_A + 2 * A_BYTES, hsrc + 2 * KCH, warp, lane);

        // ---- 16-chunk GEMM: no CTA barriers; fragments double-buffered ----
#pragma unroll
        for (int c = 0; c < NCHUNK; ++c) {
            if (c + 3 < NCHUNK)
                issue_chunk_w(smem_u + OFF_A + ((c + 3) & 3) * A_BYTES,
                              hsrc + (c + 3) * KCH, warp, lane);
            if (c < NCHUNK - 3)      { CP_WAIT(3); }
            else if (c == NCHUNK - 3){ CP_WAIT(2); }
            else if (c == NCHUNK - 2){ CP_WAIT(1); }
            else                     { CP_WAIT(0); }

            const uint32_t abase = smem_u + OFF_A + (uint32_t)((c & 3) * A_BYTES) + a_byte;
            const uint32_t wbase = smem_u + OFF_W + w_byte + (uint32_t)(c * (KCH * WS_STR * 2));

            uint32_t av0[4], av1[4], bv0[4], bv1[4];
            ldsm4(av0, abase);
            ldsm4t(bv0, wbase);
#pragma unroll
            for (int kk = 0; kk < 4; ++kk) {
                uint32_t* avc = (kk & 1) ? av1 : av0;
                uint32_t* avn = (kk & 1) ? av0 : av1;
                if (kk < 3) ldsm4(avn, abase + (uint32_t)((kk + 1) * 32));
#pragma unroll
                for (int j = 0; j < 4; ++j) {
                    const int idx = kk * 4 + j;
                    uint32_t* bvc = (idx & 1) ? bv1 : bv0;
                    uint32_t* bvn = (idx & 1) ? bv0 : bv1;
                    if (idx < 15) {
                        const int ni = idx + 1;
                        ldsm4t(bvn, wbase + (uint32_t)((ni >> 2) * (16 * WS_STR * 2)
                                                       + (ni & 3) * 32));
                    }
                    mma16816(acc[2 * j],     avc, bvc + 0);
                    mma16816(acc[2 * j + 1], avc, bvc + 2);
                }
            }
        }

        // ---- epilogue: per-warp, immediately (no CTA barrier needed) ----
        const bool last = (t == SQ - 1);
        if (last) __syncthreads();   // protect hs region (aliases A buf 0)
#pragma unroll
        for (int m = 0; m < 2; ++m) {
            const int r = r0_ + 8 * m;
            const float xv = g_xT[t * BBat + rowbase + r];
            float hv[4];
#pragma unroll
            for (int uu = 0; uu < 4; ++uu) {
                const int nfb = uu >> 1;           // u>>3
                const int e   = 2 * m + (uu & 1);  // frag elem
                float zg = acc[0 + nfb][e] + xv * wxr[0][uu] + brr[0][uu];
                float zi = acc[2 + nfb][e] + xv * wxr[1][uu] + brr[1][uu];
                float zf = acc[4 + nfb][e] + xv * wxr[2][uu] + brr[2][uu];
                float zo = acc[6 + nfb][e] + xv * wxr[3][uu] + brr[3][uu];
                float gg = tanh_ap(zg);
                float ii = sig_ap(zi);
                float ff = sig_ap(zf);
                float oo = sig_ap(zo);
                float cn = gg * ii + cst[m][uu] * ff;
                cst[m][uu] = cn;
                hv[uu] = tanh_ap(cn) * oo;
                if (last) hs[r * UNITS + ulist[uu]] = hv[uu];
            }
            __half* hp = &hdst[(size_t)(rowbase + r) * Hh + j0h];
            *(__half2*)&hp[2 * a_]     = __floats2half2_rn(hv[0], hv[1]);
            *(__half2*)&hp[2 * a_ + 8] = __floats2half2_rn(hv[2], hv[3]);
        }

        if (last) {
            __syncthreads();
            if (tid < BH) {
                int r = tid;
                float s[CCls];
#pragma unroll
                for (int cl = 0; cl < CCls; ++cl) s[cl] = 0.0f;
#pragma unroll
                for (int u2 = 0; u2 < UNITS; ++u2) {
                    float hvv = hs[r * UNITS + u2];
#pragma unroll
                    for (int cl = 0; cl < CCls; ++cl) s[cl] += hvv * wph_s[u2 * CCls + cl];
                }
#pragma unroll
                for (int cl = 0; cl < CCls; ++cl)
                    atomicAdd(&out[(rowbase + r) * CCls + cl], s[cl]);
            }
        }

        // publish step-t h for my half (h stores of all warps ordered by barrier)
        __syncthreads();
        if (tid == 0) { __threadfence(); atomicAdd(&g_wrc[b_half * 8 + (col_tile & 7)], 1u); }
    }

    // final full barrier, then reset monotonic counters for the next graph replay
    gsync(ls);   // barrier #2 (even count -> g_sense back to 0)
    if (bid == 0 && tid == 0) {
#pragma unroll
        for (int j = 0; j < 16; ++j) g_wrc[j] = 0;
        __threadfence();
    }
}

// ---------------- launch ----------------
extern "C" void kernel_launch(void* const* d_in, const int* in_sizes, int n_in,
                              void* d_out, int out_size)
{
    const float* x   = (const float*)d_in[0];
    const float* wgx = (const float*)d_in[1];
    const float* wix = (const float*)d_in[2];
    const float* wfx = (const float*)d_in[3];
    const float* wox = (const float*)d_in[4];
    const float* wgh = (const float*)d_in[5];
    const float* wih = (const float*)d_in[6];
    const float* wfh = (const float*)d_in[7];
    const float* woh = (const float*)d_in[8];
    const float* wph = (const float*)d_in[9];
    const float* bg  = (const float*)d_in[10];
    const float* bi  = (const float*)d_in[11];
    const float* bf_ = (const float*)d_in[12];
    const float* bo  = (const float*)d_in[13];
    const float* bp  = (const float*)d_in[14];
    float* out = (float*)d_out;

    cudaFuncSetAttribute(lstm_persistent_kernel,
                         cudaFuncAttributeMaxDynamicSharedMemorySize, SMEM_BYTES);

    lstm_persistent_kernel<<<NCTA, TPB, SMEM_BYTES>>>(
        x, wgx, wix, wfx, wox, wgh, wih, wfh, woh, wph,
        bg, bi, bf_, bo, bp, out);
}